// round 5
// baseline (speedup 1.0000x reference)
#include <cuda_runtime.h>
#include <cstdint>
#include <math.h>

#define HH 256
#define MM 32
#define NIMG 512
#define NMODES (NIMG*MM*MM)

typedef unsigned long long u64;

// ---------- scratch ----------
__device__ float2 g_modes[2][NIMG][MM * MM]; // [sel][img][k2*32+k1]
__device__ float  g_totp[NIMG * 2];          // per-image energy partials (khalf)
__device__ double g_part[8][1024][6];        // k_spec partials

// ---------- f32x2 helpers ----------
__device__ __forceinline__ u64 pack2(float lo, float hi) {
    u64 r; asm("mov.b64 %0,{%1,%2};" : "=l"(r) : "f"(lo), "f"(hi)); return r;
}
__device__ __forceinline__ void unpack2(u64 v, float& lo, float& hi) {
    asm("mov.b64 {%0,%1},%2;" : "=f"(lo), "=f"(hi) : "l"(v));
}
__device__ __forceinline__ u64 ffma2(u64 a, u64 b, u64 c) {
    u64 d; asm("fma.rn.f32x2 %0,%1,%2,%3;" : "=l"(d) : "l"(a), "l"(b), "l"(c)); return d;
}
__device__ __forceinline__ u64 fmul2(u64 a, u64 b) {
    u64 d; asm("mul.rn.f32x2 %0,%1,%2;" : "=l"(d) : "l"(a), "l"(b)); return d;
}

// ============================================================================
// K1: partial 2D DFT. grid (512 img, 2 sel, 2 khalf), 256 thr, 4 blocks/SM.
// Each block: 16 k1 x 256 n2 (stage 1), then 16 k1 x 32 k2 (stage 2).
// smem (41024B dynamic):
//   [0,2048)      s_twc u64[256]  (cos,cos)
//   [2048,4096)   s_tws u64[256]  (-sin,-sin)
//   [4096,5120)   s_cosf f32[256]
//   [5120,6144)   s_sinf f32[256]
//   [6144,40992)  UNION: stage1 staging s_x f32[8192] (32KB)
//                 | s_Pr u64[128*17] + s_Pi u64[128*17] (34816B, post-loop)
//   [40992,41024) s_red f32[8]
// ============================================================================
extern __shared__ char smem8[];

__global__ void __launch_bounds__(256, 4)
k_dft(const float* __restrict__ pred, const float* __restrict__ gt)
{
    const int img   = blockIdx.x;
    const int sel   = blockIdx.y;
    const int kbase = blockIdx.z * 16;
    const float* __restrict__ x = (sel ? gt : pred) + (size_t)img * (HH * HH);

    u64*   s_twc  = (u64*)smem8;
    u64*   s_tws  = (u64*)(smem8 + 2048);
    float* s_cosf = (float*)(smem8 + 4096);
    float* s_sinf = (float*)(smem8 + 5120);
    float* s_x    = (float*)(smem8 + 6144);       // staging, 8192 floats
    u64*   s_Pr   = (u64*)(smem8 + 6144);         // aliases s_x (post-loop)
    u64*   s_Pi   = s_Pr + 128 * 17;
    float* s_red  = (float*)(smem8 + 40992);

    const int tid = threadIdx.x;

    // twiddle tables
    {
        float sn, cs;
        sincospif((float)tid * (1.0f / 128.0f), &sn, &cs);
        s_twc[tid] = pack2(cs, cs);
        s_tws[tid] = pack2(-sn, -sn);
        s_cosf[tid] = cs;
        s_sinf[tid] = sn;
    }

    // ---- stage 1 ----
    const int q = tid & 31;        // n2-pair lane: u64 index q + 32j
    const int p = tid >> 5;        // k1 = kbase + p (+8)
    const int k1a = kbase + p, k1b = kbase + p + 8;

    u64 accR[2][4], accI[2][4];
#pragma unroll
    for (int m = 0; m < 2; m++)
#pragma unroll
        for (int j = 0; j < 4; j++) { accR[m][j] = 0ull; accI[m][j] = 0ull; }

    __syncthreads();   // twiddle tables ready

    const float4* gsrc = (const float4*)x;  // 4096 float4 total
    for (int c = 0; c < 8; c++) {
        // stage 32 rows (8192 floats = 2048 float4), 8 float4 per thread
        float4* dst = (float4*)s_x;
        const float4* src = gsrc + (size_t)c * 2048;
#pragma unroll
        for (int i = 0; i < 8; i++)
            dst[i * 256 + tid] = src[i * 256 + tid];
        __syncthreads();

        const u64* xb = (const u64*)s_x;
#pragma unroll 4
        for (int r = 0; r < 32; r++) {
            const int n1 = c * 32 + r;
            const int i0 = (k1a * n1) & 255;
            const int i1 = (k1b * n1) & 255;
            const u64 cc0 = s_twc[i0], ns0 = s_tws[i0];
            const u64 cc1 = s_twc[i1], ns1 = s_tws[i1];
            const u64* row = xb + r * 128 + q;
            const u64 x0 = row[0], x1 = row[32], x2 = row[64], x3 = row[96];
            accR[0][0] = ffma2(x0, cc0, accR[0][0]); accI[0][0] = ffma2(x0, ns0, accI[0][0]);
            accR[0][1] = ffma2(x1, cc0, accR[0][1]); accI[0][1] = ffma2(x1, ns0, accI[0][1]);
            accR[0][2] = ffma2(x2, cc0, accR[0][2]); accI[0][2] = ffma2(x2, ns0, accI[0][2]);
            accR[0][3] = ffma2(x3, cc0, accR[0][3]); accI[0][3] = ffma2(x3, ns0, accI[0][3]);
            accR[1][0] = ffma2(x0, cc1, accR[1][0]); accI[1][0] = ffma2(x0, ns1, accI[1][0]);
            accR[1][1] = ffma2(x1, cc1, accR[1][1]); accI[1][1] = ffma2(x1, ns1, accI[1][1]);
            accR[1][2] = ffma2(x2, cc1, accR[1][2]); accI[1][2] = ffma2(x2, ns1, accI[1][2]);
            accR[1][3] = ffma2(x3, cc1, accR[1][3]); accI[1][3] = ffma2(x3, ns1, accI[1][3]);
        }
        __syncthreads();
    }

    // scatter pairs: s_P[pair][k1loc]; pair p2=q+32j covers n2=(2p2, 2p2+1)
#pragma unroll
    for (int m = 0; m < 2; m++)
#pragma unroll
        for (int j = 0; j < 4; j++) {
            const int pr = (q + 32 * j) * 17 + (p + 8 * m);
            s_Pr[pr] = accR[m][j];
            s_Pi[pr] = accI[m][j];
        }
    __syncthreads();

    // ---- stage 2: thread = (k2 = tid>>3, nsub = tid&7); 16 pairs, 16 k1 ----
    const int k2   = tid >> 3;
    const int nsub = tid & 7;

    // twiddle init + rotation delta (angle step per i: 16*k2 table units)
    const int a0 = (k2 * 2 * nsub) & 255;
    const int a1 = (a0 + k2) & 255;
    const u64 c2_0 = pack2(s_cosf[a0], s_cosf[a1]);
    const u64 s2_0 = pack2(s_sinf[a0], s_sinf[a1]);
    const int ad = (16 * k2) & 255;
    const float cdv = s_cosf[ad], sdv = s_sinf[ad];
    const u64 cd2  = pack2(cdv, cdv);
    const u64 sd2  = pack2(sdv, sdv);
    const u64 nsd2 = pack2(-sdv, -sdv);

    float2* __restrict__ outm = g_modes[sel][img];
    float esum = 0.f;

#pragma unroll 1
    for (int pass = 0; pass < 4; pass++) {
        u64 re2[4] = {0,0,0,0}, ia2[4] = {0,0,0,0}, ib2[4] = {0,0,0,0};
        u64 c2 = c2_0, s2 = s2_0;
#pragma unroll 4
        for (int i = 0; i < 16; i++) {
            const int p2 = nsub + 8 * i;
            const u64* pr = s_Pr + p2 * 17 + pass * 4;
            const u64* pi = s_Pi + p2 * 17 + pass * 4;
#pragma unroll
            for (int kk = 0; kk < 4; kk++) {
                const u64 xr2 = pr[kk], xi2 = pi[kk];
                re2[kk] = ffma2(xr2, c2, re2[kk]);   // re += Xr*c
                re2[kk] = ffma2(xi2, s2, re2[kk]);   // re += Xi*s
                ia2[kk] = ffma2(xi2, c2, ia2[kk]);   // im+ = Xi*c
                ib2[kk] = ffma2(xr2, s2, ib2[kk]);   // im- = Xr*s
            }
            // rotate twiddle by delta
            const u64 cn = ffma2(s2, nsd2, fmul2(c2, cd2));
            const u64 sn = ffma2(c2, sd2,  fmul2(s2, cd2));
            c2 = cn; s2 = sn;
        }
#pragma unroll
        for (int kk = 0; kk < 4; kk++) {
            float rl, rh, al, ah, bl, bh;
            unpack2(re2[kk], rl, rh);
            unpack2(ia2[kk], al, ah);
            unpack2(ib2[kk], bl, bh);
            float re = rl + rh;
            float im = (al + ah) - (bl + bh);
            re += __shfl_xor_sync(0xffffffffu, re, 1);
            re += __shfl_xor_sync(0xffffffffu, re, 2);
            re += __shfl_xor_sync(0xffffffffu, re, 4);
            im += __shfl_xor_sync(0xffffffffu, im, 1);
            im += __shfl_xor_sync(0xffffffffu, im, 2);
            im += __shfl_xor_sync(0xffffffffu, im, 4);
            if (nsub == 0) {
                const int kg = kbase + pass * 4 + kk;
                outm[k2 * 32 + kg] = make_float2(re, im);
                esum = fmaf(re, re, fmaf(im, im, esum));
            }
        }
    }

    if (sel == 0) {
        float e = esum;  // nonzero only where nsub==0
#pragma unroll
        for (int off = 16; off; off >>= 1)
            e += __shfl_xor_sync(0xffffffffu, e, off);
        if ((tid & 31) == 0) s_red[tid >> 5] = e;
        __syncthreads();
        if (tid == 0) {
            float t = 0.f;
            for (int w = 0; w < 8; w++) t += s_red[w];
            g_totp[img * 2 + blockIdx.z] = t;
        }
    }
}

// ============================================================================
// K3: pointwise + per-mode MLP. grid (512,4) x 256.
// ============================================================================
__global__ void __launch_bounds__(256)
k_mlp(const float* __restrict__ W1, const float* __restrict__ b1,
      const float* __restrict__ W2, const float* __restrict__ b2,
      const float* __restrict__ W3, const float* __restrict__ b3,
      float* __restrict__ o_energy, float* __restrict__ o_unc,
      float* __restrict__ o_frac,   float* __restrict__ o_weight,
      float* __restrict__ o_err)
{
    __shared__ float sW1[128], sb1[64], sb2[32], sW3[32];
    __shared__ float sb3;
    __shared__ u64 sW2t[1024];

    const int tid = threadIdx.x;
    if (tid < 128) sW1[tid] = W1[tid];
    if (tid < 64)  sb1[tid] = b1[tid];
    if (tid < 32)  { sb2[tid] = b2[tid]; sW3[tid] = W3[tid]; }
    if (tid == 0)  sb3 = b3[0];
    for (int idx = tid; idx < 1024; idx += 256) {
        const int i = idx >> 5, jj = idx & 31;
        sW2t[idx] = pack2(W2[(2 * jj) * 32 + i], W2[(2 * jj + 1) * 32 + i]);
    }
    __syncthreads();

    const int img  = blockIdx.x;
    const int midx = blockIdx.y * 256 + tid;   // k1*32 + k2
    const int k1 = midx >> 5, k2 = midx & 31;

    const float2 mp = g_modes[0][img][k2 * 32 + k1];
    const float2 mg = g_modes[1][img][k2 * 32 + k1];

    const float energy = mp.x * mp.x + mp.y * mp.y;
    const float dr = mp.x - mg.x, di = mp.y - mg.y;
    const float err = dr * dr + di * di;

    u64 h1p[32];
#pragma unroll
    for (int jj = 0; jj < 32; jj++) {
        const float a = fmaxf(fmaf(mp.y, sW1[64 + 2 * jj],
                              fmaf(mp.x, sW1[2 * jj], sb1[2 * jj])), 0.f);
        const float b = fmaxf(fmaf(mp.y, sW1[64 + 2 * jj + 1],
                              fmaf(mp.x, sW1[2 * jj + 1], sb1[2 * jj + 1])), 0.f);
        h1p[jj] = pack2(a, b);
    }

    float out = sb3;
    for (int i = 0; i < 32; i++) {
        u64 a2 = 0ull;
#pragma unroll
        for (int jj = 0; jj < 32; jj++)
            a2 = ffma2(h1p[jj], sW2t[i * 32 + jj], a2);
        float alo, ahi; unpack2(a2, alo, ahi);
        const float h2 = fmaxf(alo + ahi + sb2[i], 0.f);
        out = fmaf(h2, sW3[i], out);
    }
    const float uval = fmaxf(out, 0.f) + log1pf(expf(-fabsf(out)));

    const float tot  = g_totp[img * 2] + g_totp[img * 2 + 1];
    const float frac = energy / (tot + 1e-8f);

    const size_t base = (size_t)img * 1024 + midx;
    o_energy[base] = energy;
    o_unc[base]    = uval;
    o_frac[base]   = frac;
    o_weight[base] = frac * uval;
    o_err[base]    = err;
}

// ============================================================================
// K4a: partial stats; grid (32 modegrp, 8 imggrp) x 1024.
// ============================================================================
__global__ void __launch_bounds__(1024)
k_spec_part(const float* __restrict__ o_unc, const float* __restrict__ o_err,
            const float* __restrict__ o_energy)
{
    __shared__ double sp[32][32][6];
    const int tid = threadIdx.x;
    const int m = tid & 31, grp = tid >> 5;
    const int mode = blockIdx.x * 32 + m;
    const int ig = blockIdx.y;

    double su = 0, se = 0, sen = 0, suu = 0, see = 0, sue = 0;
    for (int img = ig * 64 + grp; img < (ig + 1) * 64; img += 32) {
        const size_t off = (size_t)img * 1024 + mode;
        const double u  = o_unc[off];
        const double e  = o_err[off];
        const double en = o_energy[off];
        su += u; se += e; sen += en;
        suu += u * u; see += e * e; sue += u * e;
    }
    sp[grp][m][0] = su;  sp[grp][m][1] = se;  sp[grp][m][2] = sen;
    sp[grp][m][3] = suu; sp[grp][m][4] = see; sp[grp][m][5] = sue;
    __syncthreads();

    if (tid < 32) {
        double a[6] = {0, 0, 0, 0, 0, 0};
        for (int g2 = 0; g2 < 32; g2++)
#pragma unroll
            for (int s = 0; s < 6; s++) a[s] += sp[g2][tid][s];
        const int md = blockIdx.x * 32 + tid;
#pragma unroll
        for (int s = 0; s < 6; s++) g_part[ig][md][s] = a[s];
    }
}

// K4b: finalize. <<<1, 1024>>>
__global__ void __launch_bounds__(1024)
k_spec_fin(float* __restrict__ o_uspec, float* __restrict__ o_espec,
           float* __restrict__ o_calib)
{
    const int md = threadIdx.x;
    double a0 = 0, a1 = 0, a2 = 0, a3 = 0, a4 = 0, a5 = 0;
    for (int ig = 0; ig < 8; ig++) {
        a0 += g_part[ig][md][0]; a1 += g_part[ig][md][1]; a2 += g_part[ig][md][2];
        a3 += g_part[ig][md][3]; a4 += g_part[ig][md][4]; a5 += g_part[ig][md][5];
    }
    const double N = (double)NIMG;
    o_uspec[md] = (float)(a0 / N);
    o_espec[md] = (float)(a2 / N);
    const double num = a5 - a0 * a1 / N;
    const double A   = a3 - a0 * a0 / N;
    const double Bv  = a4 - a1 * a1 / N;
    const double den = sqrt(fmax(A * Bv, 0.0));
    o_calib[md] = (float)(num / (den + 1e-8));
}

// ============================================================================
// launch
// ============================================================================
extern "C" void kernel_launch(void* const* d_in, const int* in_sizes, int n_in,
                              void* d_out, int out_size)
{
    const float* pred = (const float*)d_in[0];
    const float* gt   = (const float*)d_in[2];
    const float* W1 = (const float*)d_in[3];
    const float* b1 = (const float*)d_in[4];
    const float* W2 = (const float*)d_in[5];
    const float* b2 = (const float*)d_in[6];
    const float* W3 = (const float*)d_in[7];
    const float* b3 = (const float*)d_in[8];

    float* out = (float*)d_out;
    const size_t NM = (size_t)NMODES;
    float* o_energy = out;
    float* o_unc    = out + NM;
    float* o_frac   = out + 2 * NM;
    float* o_weight = out + 3 * NM;
    float* o_uspec  = out + 4 * NM;
    float* o_espec  = o_uspec + 1024;
    float* o_err    = o_espec + 1024;
    float* o_calib  = o_err + NM;

    const int smem_dft = 41024;
    cudaFuncSetAttribute(k_dft, cudaFuncAttributeMaxDynamicSharedMemorySize, smem_dft);

    k_dft<<<dim3(NIMG, 2, 2), 256, smem_dft>>>(pred, gt);
    k_mlp<<<dim3(NIMG, 4), 256>>>(W1, b1, W2, b2, W3, b3,
                                  o_energy, o_unc, o_frac, o_weight, o_err);
    k_spec_part<<<dim3(32, 8), 1024>>>(o_unc, o_err, o_energy);
    k_spec_fin<<<1, 1024>>>(o_uspec, o_espec, o_calib);
}